// round 2
// baseline (speedup 1.0000x reference)
#include <cuda_runtime.h>
#include <cuda_bf16.h>

#define TILE  128
#define HALO  12
#define KWIN  9
#define DIL   3
#define HD    32
#define KV_W  (TILE + 2*HALO)   /* 152 */
#define KV_G  (KV_W / 4)        /* 38 float4 groups per channel */
#define ROW   36                /* padded row stride (floats): conflict-free LDS.128 */

typedef unsigned long long u64;

__device__ __forceinline__ u64 pack2(float a, float b) {
    u64 r; asm("mov.b64 %0, {%1, %2};" : "=l"(r) : "f"(a), "f"(b)); return r;
}
__device__ __forceinline__ void unpack2(u64 p, float& a, float& b) {
    asm("mov.b64 {%0, %1}, %2;" : "=f"(a), "=f"(b) : "l"(p));
}
__device__ __forceinline__ u64 fma2(u64 a, u64 b, u64 c) {
    u64 d; asm("fma.rn.f32x2 %0, %1, %2, %3;" : "=l"(d) : "l"(a), "l"(b), "l"(c)); return d;
}

// bounds-checked float4 load of elements n..n+3 from a length-L row (zero-fill OOB)
__device__ __forceinline__ float4 ld4(const float* __restrict__ row, int n, int L) {
    if (n >= 0 && n + 3 < L) return *(const float4*)(row + n);
    float4 r;
    r.x = ((unsigned)(n + 0) < (unsigned)L) ? row[n + 0] : 0.f;
    r.y = ((unsigned)(n + 1) < (unsigned)L) ? row[n + 1] : 0.f;
    r.z = ((unsigned)(n + 2) < (unsigned)L) ? row[n + 2] : 0.f;
    r.w = ((unsigned)(n + 3) < (unsigned)L) ? row[n + 3] : 0.f;
    return r;
}

__global__ __launch_bounds__(TILE, 8)
void dilated_attn_kernel(const float* __restrict__ q,
                         const float* __restrict__ k,
                         const float* __restrict__ v,
                         float* __restrict__ out,
                         int B, int d, int L)
{
    __shared__ float kv_s[KV_W][ROW];   // single buffer, reused for K then V

    const int t    = threadIdx.x;
    const int tile = blockIdx.x & 31;          // L/TILE = 32 tiles
    const int h    = (blockIdx.x >> 5) & 15;   // 16 heads
    const int b    = blockIdx.x >> 9;          // 4 batches
    const int n0   = tile * TILE;
    const int n    = n0 + t;

    const long chan_base = ((long)b * d + h * HD) * L;
    const float* kb = k + chan_base;
    const float* vb = v + chan_base;
    const float* qb = q + chan_base;

    // ---- Pass 1: stage K tile (transposed, halo zero-filled = Unfold padding) ----
    #pragma unroll
    for (int it = 0; it < 10; it++) {
        const int idx = t + it * TILE;
        if (idx < HD * KV_G) {
            const int c  = idx / KV_G;
            const int g  = idx - c * KV_G;
            const int nl = g * 4;
            const float4 x = ld4(kb + (long)c * L, n0 - HALO + nl, L);
            kv_s[nl + 0][c] = x.x;
            kv_s[nl + 1][c] = x.y;
            kv_s[nl + 2][c] = x.z;
            kv_s[nl + 3][c] = x.w;
        }
    }
    __syncthreads();

    // ---- QK^T over 9-wide dilated window (packed f32x2 FMAs) ----
    u64 acc2[KWIN];
    #pragma unroll
    for (int kk = 0; kk < KWIN; kk++) acc2[kk] = 0ull;

    #pragma unroll
    for (int c4 = 0; c4 < HD / 4; c4++) {
        const float q0 = qb[(long)(c4 * 4 + 0) * L + n];
        const float q1 = qb[(long)(c4 * 4 + 1) * L + n];
        const float q2 = qb[(long)(c4 * 4 + 2) * L + n];
        const float q3 = qb[(long)(c4 * 4 + 3) * L + n];
        const u64 q01 = pack2(q0, q1);
        const u64 q23 = pack2(q2, q3);
        #pragma unroll
        for (int kk = 0; kk < KWIN; kk++) {
            const float4 kvv = *(const float4*)&kv_s[t + DIL * kk][c4 * 4];
            acc2[kk] = fma2(q01, pack2(kvv.x, kvv.y), acc2[kk]);
            acc2[kk] = fma2(q23, pack2(kvv.z, kvv.w), acc2[kk]);
        }
    }

    // ---- softmax over 9 ----
    const float scale = 0.17677669529663687f;   // 32^-0.5
    float s[KWIN];
    float mx = -1e30f;
    #pragma unroll
    for (int kk = 0; kk < KWIN; kk++) {
        float lo, hi; unpack2(acc2[kk], lo, hi);
        s[kk] = (lo + hi) * scale;
        mx = fmaxf(mx, s[kk]);
    }
    float sum = 0.f;
    #pragma unroll
    for (int kk = 0; kk < KWIN; kk++) { s[kk] = __expf(s[kk] - mx); sum += s[kk]; }
    const float inv = 1.f / sum;
    u64 w2[KWIN];
    #pragma unroll
    for (int kk = 0; kk < KWIN; kk++) { const float w = s[kk] * inv; w2[kk] = pack2(w, w); }

    // ---- Pass 2: restage V into the same buffer ----
    __syncthreads();   // everyone done reading K
    #pragma unroll
    for (int it = 0; it < 10; it++) {
        const int idx = t + it * TILE;
        if (idx < HD * KV_G) {
            const int c  = idx / KV_G;
            const int g  = idx - c * KV_G;
            const int nl = g * 4;
            const float4 x = ld4(vb + (long)c * L, n0 - HALO + nl, L);
            kv_s[nl + 0][c] = x.x;
            kv_s[nl + 1][c] = x.y;
            kv_s[nl + 2][c] = x.z;
            kv_s[nl + 3][c] = x.w;
        }
    }
    __syncthreads();

    // ---- attn @ V (packed f32x2) ----
    u64 o2[HD / 2];
    #pragma unroll
    for (int c2 = 0; c2 < HD / 2; c2++) o2[c2] = 0ull;

    #pragma unroll
    for (int kk = 0; kk < KWIN; kk++) {
        #pragma unroll
        for (int c4 = 0; c4 < HD / 4; c4++) {
            const float4 vv = *(const float4*)&kv_s[t + DIL * kk][c4 * 4];
            o2[c4 * 2 + 0] = fma2(w2[kk], pack2(vv.x, vv.y), o2[c4 * 2 + 0]);
            o2[c4 * 2 + 1] = fma2(w2[kk], pack2(vv.z, vv.w), o2[c4 * 2 + 1]);
        }
    }

    // ---- store: out[b][0][n][h*32 + c], 32 contiguous floats -> 8x STG.128 ----
    float4* op = (float4*)(out + ((long)b * L + n) * d + h * HD);
    #pragma unroll
    for (int c4 = 0; c4 < HD / 4; c4++) {
        float4 r;
        unpack2(o2[c4 * 2 + 0], r.x, r.y);
        unpack2(o2[c4 * 2 + 1], r.z, r.w);
        op[c4] = r;
    }
}

extern "C" void kernel_launch(void* const* d_in, const int* in_sizes, int n_in,
                              void* d_out, int out_size)
{
    const float* q = (const float*)d_in[0];
    const float* k = (const float*)d_in[1];
    const float* v = (const float*)d_in[2];
    float* out = (float*)d_out;

    const int B = 4, d = 512, L = 4096;
    const int grid = B * (d / HD) * (L / TILE);   // 2048
    dilated_attn_kernel<<<grid, TILE>>>(q, k, v, out, B, d, L);
}

// round 3
// speedup vs baseline: 1.0492x; 1.0492x over previous
#include <cuda_runtime.h>
#include <cuda_bf16.h>

#define TILE  128
#define HALO  12
#define KWIN  9
#define DIL   3
#define HD    32
#define KV_W  (TILE + 2*HALO)   /* 152 */
#define KV_G  (KV_W / 4)        /* 38 float4 groups per channel */
#define ROW   36                /* padded row stride: conflict-free LDS.128 */

typedef unsigned long long u64;

__device__ __forceinline__ u64 pack2(float a, float b) {
    u64 r; asm("mov.b64 %0, {%1, %2};" : "=l"(r) : "f"(a), "f"(b)); return r;
}
__device__ __forceinline__ void unpack2(u64 p, float& a, float& b) {
    asm("mov.b64 {%0, %1}, %2;" : "=f"(a), "=f"(b) : "l"(p));
}
__device__ __forceinline__ u64 fma2(u64 a, u64 b, u64 c) {
    u64 d; asm("fma.rn.f32x2 %0, %1, %2, %3;" : "=l"(d) : "l"(a), "l"(b), "l"(c)); return d;
}

// bounds-checked float4 load of elements n..n+3 (zero-fill OOB = Unfold padding)
__device__ __forceinline__ float4 ld4(const float* __restrict__ row, int n, int L) {
    if (n >= 0 && n + 3 < L) return *(const float4*)(row + n);
    float4 r;
    r.x = ((unsigned)(n + 0) < (unsigned)L) ? row[n + 0] : 0.f;
    r.y = ((unsigned)(n + 1) < (unsigned)L) ? row[n + 1] : 0.f;
    r.z = ((unsigned)(n + 2) < (unsigned)L) ? row[n + 2] : 0.f;
    r.w = ((unsigned)(n + 3) < (unsigned)L) ? row[n + 3] : 0.f;
    return r;
}

__global__ __launch_bounds__(TILE, 5)
void dilated_attn_kernel(const float* __restrict__ q,
                         const float* __restrict__ k,
                         const float* __restrict__ v,
                         float* __restrict__ out,
                         int B, int d, int L)
{
    __shared__ float ks[KV_W][ROW];
    __shared__ float vs[KV_W][ROW];

    const int t    = threadIdx.x;
    const int tile = blockIdx.x & 31;          // L/TILE = 32
    const int h    = (blockIdx.x >> 5) & 15;   // 16 heads
    const int b    = blockIdx.x >> 9;          // 4 batches
    const int n0   = tile * TILE;
    const int n    = n0 + t;

    const long chan_base = ((long)b * d + h * HD) * L;
    const float* kb = k + chan_base;
    const float* vb = v + chan_base;
    const float* qb = q + chan_base;

    // ---- prefetch q into packed registers (overlaps staging DRAM latency) ----
    u64 q2[HD / 2];
    #pragma unroll
    for (int c2 = 0; c2 < HD / 2; c2++) {
        const float a = qb[(long)(2 * c2 + 0) * L + n];
        const float bq = qb[(long)(2 * c2 + 1) * L + n];
        q2[c2] = pack2(a, bq);
    }

    // ---- stage K and V tiles together (one barrier for the whole kernel) ----
    #pragma unroll
    for (int it = 0; it < 10; it++) {
        const int idx = t + it * TILE;
        if (idx < HD * KV_G) {
            const int c  = idx / KV_G;
            const int g  = idx - c * KV_G;
            const int nl = g * 4;
            const int ng = n0 - HALO + nl;
            const float4 xk = ld4(kb + (long)c * L, ng, L);
            const float4 xv = ld4(vb + (long)c * L, ng, L);
            ks[nl + 0][c] = xk.x;  ks[nl + 1][c] = xk.y;
            ks[nl + 2][c] = xk.z;  ks[nl + 3][c] = xk.w;
            vs[nl + 0][c] = xv.x;  vs[nl + 1][c] = xv.y;
            vs[nl + 2][c] = xv.z;  vs[nl + 3][c] = xv.w;
        }
    }
    __syncthreads();

    // ---- QK^T over the 9-wide dilated window (f32x2 packed FMAs) ----
    u64 acc2[KWIN];
    #pragma unroll
    for (int kk = 0; kk < KWIN; kk++) acc2[kk] = 0ull;

    #pragma unroll
    for (int c4 = 0; c4 < HD / 4; c4++) {
        const u64 q01 = q2[c4 * 2 + 0];
        const u64 q23 = q2[c4 * 2 + 1];
        #pragma unroll
        for (int kk = 0; kk < KWIN; kk++) {
            const float4 kvv = *(const float4*)&ks[t + DIL * kk][c4 * 4];
            acc2[kk] = fma2(q01, pack2(kvv.x, kvv.y), acc2[kk]);
            acc2[kk] = fma2(q23, pack2(kvv.z, kvv.w), acc2[kk]);
        }
    }

    // ---- softmax over 9 ----
    const float scale = 0.17677669529663687f;   // 32^-0.5
    float s[KWIN];
    float mx = -1e30f;
    #pragma unroll
    for (int kk = 0; kk < KWIN; kk++) {
        float lo, hi; unpack2(acc2[kk], lo, hi);
        s[kk] = (lo + hi) * scale;
        mx = fmaxf(mx, s[kk]);
    }
    float sum = 0.f;
    #pragma unroll
    for (int kk = 0; kk < KWIN; kk++) { s[kk] = __expf(s[kk] - mx); sum += s[kk]; }
    const float inv = 1.f / sum;
    u64 w2[KWIN];
    #pragma unroll
    for (int kk = 0; kk < KWIN; kk++) { const float w = s[kk] * inv; w2[kk] = pack2(w, w); }

    // ---- attn @ V ----
    u64 o2[HD / 2];
    #pragma unroll
    for (int c2 = 0; c2 < HD / 2; c2++) o2[c2] = 0ull;

    #pragma unroll
    for (int kk = 0; kk < KWIN; kk++) {
        #pragma unroll
        for (int c4 = 0; c4 < HD / 4; c4++) {
            const float4 vv = *(const float4*)&vs[t + DIL * kk][c4 * 4];
            o2[c4 * 2 + 0] = fma2(w2[kk], pack2(vv.x, vv.y), o2[c4 * 2 + 0]);
            o2[c4 * 2 + 1] = fma2(w2[kk], pack2(vv.z, vv.w), o2[c4 * 2 + 1]);
        }
    }

    // ---- store: out[b][0][n][h*32+c] -> 8x STG.128 per thread ----
    float4* op = (float4*)(out + ((long)b * L + n) * d + h * HD);
    #pragma unroll
    for (int c4 = 0; c4 < HD / 4; c4++) {
        float4 r;
        unpack2(o2[c4 * 2 + 0], r.x, r.y);
        unpack2(o2[c4 * 2 + 1], r.z, r.w);
        op[c4] = r;
    }
}

extern "C" void kernel_launch(void* const* d_in, const int* in_sizes, int n_in,
                              void* d_out, int out_size)
{
    const float* q = (const float*)d_in[0];
    const float* k = (const float*)d_in[1];
    const float* v = (const float*)d_in[2];
    float* out = (float*)d_out;

    const int B = 4, d = 512, L = 4096;
    const int grid = B * (d / HD) * (L / TILE);   // 2048
    dilated_attn_kernel<<<grid, TILE>>>(q, k, v, out, B, d, L);
}

// round 4
// speedup vs baseline: 1.3861x; 1.3212x over previous
#include <cuda_runtime.h>
#include <cuda_bf16.h>

#define TILE  128
#define HALO  12
#define KWIN  9
#define DIL   3
#define HD    32
#define KV_W  152            /* TILE + 2*HALO; div by 4, row stride in floats */
#define KV_Q  38             /* float4 quads per channel row */
#define NSTG  (HD * KV_Q)    /* 1216 staging items per matrix */

typedef unsigned long long u64;

__device__ __forceinline__ u64 pack2(float a, float b) {
    u64 r; asm("mov.b64 %0, {%1, %2};" : "=l"(r) : "f"(a), "f"(b)); return r;
}
__device__ __forceinline__ void unpack2(u64 p, float& a, float& b) {
    asm("mov.b64 {%0, %1}, %2;" : "=f"(a), "=f"(b) : "l"(p));
}
__device__ __forceinline__ u64 fma2(u64 a, u64 b, u64 c) {
    u64 d; asm("fma.rn.f32x2 %0, %1, %2, %3;" : "=l"(d) : "l"(a), "l"(b), "l"(c)); return d;
}

// bounds-checked float4 load of elements n..n+3 (zero-fill OOB = Unfold padding)
__device__ __forceinline__ float4 ld4(const float* __restrict__ row, int n, int L) {
    if (n >= 0 && n + 3 < L) return *(const float4*)(row + n);
    float4 r;
    r.x = ((unsigned)(n + 0) < (unsigned)L) ? row[n + 0] : 0.f;
    r.y = ((unsigned)(n + 1) < (unsigned)L) ? row[n + 1] : 0.f;
    r.z = ((unsigned)(n + 2) < (unsigned)L) ? row[n + 2] : 0.f;
    r.w = ((unsigned)(n + 3) < (unsigned)L) ? row[n + 3] : 0.f;
    return r;
}

__global__ __launch_bounds__(TILE, 5)
void dilated_attn_kernel(const float* __restrict__ q,
                         const float* __restrict__ k,
                         const float* __restrict__ v,
                         float* __restrict__ out,
                         int B, int d, int L)
{
    // [channel][n] layout: staging is a straight conflict-free vec4 copy,
    // compute reads are conflict-free scalar LDS (lanes = consecutive tokens).
    __shared__ float ks[HD][KV_W];
    __shared__ float vs[HD][KV_W];

    const int t    = threadIdx.x;
    const int tile = blockIdx.x & 31;          // L/TILE = 32
    const int h    = (blockIdx.x >> 5) & 15;   // 16 heads
    const int b    = blockIdx.x >> 9;          // 4 batches
    const int n0   = tile * TILE;
    const int n    = n0 + t;

    const long chan_base = ((long)b * d + h * HD) * L;
    const float* kb = k + chan_base;
    const float* vb = v + chan_base;
    const float* qb = q + chan_base;

    // ---- prefetch q into packed registers (overlaps staging DRAM latency) ----
    u64 q2[HD / 2];
    #pragma unroll
    for (int c2 = 0; c2 < HD / 2; c2++) {
        const float a  = qb[(long)(2 * c2 + 0) * L + n];
        const float bq = qb[(long)(2 * c2 + 1) * L + n];
        q2[c2] = pack2(a, bq);
    }

    // ---- stage K and V: vec4 global -> vec4 shared, no transpose ----
    #pragma unroll
    for (int it = 0; it < 10; it++) {
        const int idx = t + it * TILE;
        if (idx < NSTG) {
            const int c  = idx / KV_Q;
            const int g  = idx - c * KV_Q;
            const int ng = n0 - HALO + g * 4;
            const float4 xk = ld4(kb + (long)c * L, ng, L);
            const float4 xv = ld4(vb + (long)c * L, ng, L);
            *(float4*)&ks[c][g * 4] = xk;
            *(float4*)&vs[c][g * 4] = xv;
        }
    }
    __syncthreads();

    // ---- QK^T over the 9-wide dilated window ----
    // shared index for token t, tap kk: nl = t + 3*kk  (n0-HALO origin)
    u64 acc2[KWIN];
    #pragma unroll
    for (int kk = 0; kk < KWIN; kk++) acc2[kk] = 0ull;

    #pragma unroll
    for (int c2 = 0; c2 < HD / 2; c2++) {
        const u64 qq = q2[c2];
        const float* kr0 = &ks[2 * c2 + 0][t];
        const float* kr1 = &ks[2 * c2 + 1][t];
        #pragma unroll
        for (int kk = 0; kk < KWIN; kk++) {
            acc2[kk] = fma2(qq, pack2(kr0[DIL * kk], kr1[DIL * kk]), acc2[kk]);
        }
    }

    // ---- softmax over 9 ----
    const float scale = 0.17677669529663687f;   // 32^-0.5
    float s[KWIN];
    float mx = -1e30f;
    #pragma unroll
    for (int kk = 0; kk < KWIN; kk++) {
        float lo, hi; unpack2(acc2[kk], lo, hi);
        s[kk] = (lo + hi) * scale;
        mx = fmaxf(mx, s[kk]);
    }
    float sum = 0.f;
    #pragma unroll
    for (int kk = 0; kk < KWIN; kk++) { s[kk] = __expf(s[kk] - mx); sum += s[kk]; }
    const float inv = 1.f / sum;
    u64 w2[KWIN];
    #pragma unroll
    for (int kk = 0; kk < KWIN; kk++) { const float w = s[kk] * inv; w2[kk] = pack2(w, w); }

    // ---- attn @ V ----
    u64 o2[HD / 2];
    #pragma unroll
    for (int c2 = 0; c2 < HD / 2; c2++) o2[c2] = 0ull;

    #pragma unroll
    for (int kk = 0; kk < KWIN; kk++) {
        const u64 ww = w2[kk];
        const int nl = t + DIL * kk;
        #pragma unroll
        for (int c2 = 0; c2 < HD / 2; c2++) {
            o2[c2] = fma2(ww, pack2(vs[2 * c2 + 0][nl], vs[2 * c2 + 1][nl]), o2[c2]);
        }
    }

    // ---- store: out[b][0][n][h*32+c] -> 8x STG.128 per thread ----
    float4* op = (float4*)(out + ((long)b * L + n) * d + h * HD);
    #pragma unroll
    for (int c4 = 0; c4 < HD / 4; c4++) {
        float4 r;
        unpack2(o2[c4 * 2 + 0], r.x, r.y);
        unpack2(o2[c4 * 2 + 1], r.z, r.w);
        op[c4] = r;
    }
}

extern "C" void kernel_launch(void* const* d_in, const int* in_sizes, int n_in,
                              void* d_out, int out_size)
{
    const float* q = (const float*)d_in[0];
    const float* k = (const float*)d_in[1];
    const float* v = (const float*)d_in[2];
    float* out = (float*)d_out;

    const int B = 4, d = 512, L = 4096;
    const int grid = B * (d / HD) * (L / TILE);   // 2048
    dilated_attn_kernel<<<grid, TILE>>>(q, k, v, out, B, d, L);
}